// round 10
// baseline (speedup 1.0000x reference)
#include <cuda_runtime.h>
#include <cuda_fp16.h>
#include <math.h>
#include <stdint.h>

#define BB 2
#define LL 1024
#define HH 8
#define DD 64
#define SS 10
#define T2 20      // 2S
#define RR 128
#define KTOT 1280  // DD*T2
#define KC 64      // K per chunk
#define NCH 20     // KTOT/KC
#define MT 64      // M tile (l) per CTA

#define TSZA 8192            // 64x64 fp16 tile (128B rows, SW128)
#define TSZB 16384           // 128x64 fp16 tile
#define OFF_AQ 0
#define OFF_AK (1*TSZA)
#define OFF_BH (2*TSZA)
#define OFF_BL (2*TSZA + TSZB)
#define BUFSZ (2*TSZA + 2*TSZB)   // 48 KB
#define SMEM_BYTES (2*BUFSZ + 1024)

#define ZSCALE 64.0f         // keeps b_lo out of fp16-subnormal range
#define ZUNSCALE (1.0f/64.0f)

static __device__ __align__(16) __half g_zThi[(size_t)BB*HH*RR*KTOT];
static __device__ __align__(16) __half g_zTlo[(size_t)BB*HH*RR*KTOT];

__device__ float g_tpfr[HH*DD*SS];   // 2*pi*sigmoid(freqs)/2
__device__ float g_co[HH*DD*SS];     // cos(offsets)
__device__ float g_so[HH*DD*SS];     // sin(offsets)
__device__ float g_c1[HH*DD*SS];     // cos(tpfr)  (rotation per +1 in l)
__device__ float g_s1[HH*DD*SS];     // sin(tpfr)

// ---------------- helpers ----------------
__device__ __forceinline__ uint32_t smem_u32(const void* p) {
    uint32_t a;
    asm("{ .reg .u64 t; cvta.to.shared.u64 t, %1; cvt.u32.u64 %0, t; }" : "=r"(a) : "l"(p));
    return a;
}
__device__ __forceinline__ uint32_t swz(uint32_t b) { return b ^ ((b >> 3) & 0x70); }
__device__ __forceinline__ uint32_t h2(float x, float y) {
    __half2 h = __floats2half2_rn(x, y);
    return *(uint32_t*)&h;
}
__device__ __forceinline__ void ldsm4(uint32_t* r, uint32_t a) {
    asm volatile("ldmatrix.sync.aligned.m8n8.x4.shared.b16 {%0,%1,%2,%3}, [%4];"
        : "=r"(r[0]), "=r"(r[1]), "=r"(r[2]), "=r"(r[3]) : "r"(a));
}
__device__ __forceinline__ void mma16816(float* d, const uint32_t* a, const uint32_t* b) {
    asm volatile(
        "mma.sync.aligned.m16n8k16.row.col.f32.f16.f16.f32 "
        "{%0,%1,%2,%3}, {%4,%5,%6,%7}, {%8,%9}, {%0,%1,%2,%3};"
        : "+f"(d[0]), "+f"(d[1]), "+f"(d[2]), "+f"(d[3])
        : "r"(a[0]), "r"(a[1]), "r"(a[2]), "r"(a[3]), "r"(b[0]), "r"(b[1]));
}
__device__ __forceinline__ void cp16(uint32_t dst, const void* src) {
    asm volatile("cp.async.cg.shared.global [%0], [%1], 16;" :: "r"(dst), "l"(src) : "memory");
}

// ---------------- transpose + coef-scale -> fp16 hi/lo (+ table fill) ----------------
// z[b][h][d][t][r] (fp32) -> zT{hi,lo}[b][h][r][d*20+t] (fp16, scaled by ZSCALE)
// One block handles 2 consecutive d.
__global__ __launch_bounds__(128)
void spe_transpose(const float* __restrict__ zg,
                   const float* __restrict__ freqs,
                   const float* __restrict__ offsets,
                   const float* __restrict__ gains) {
    int dp = blockIdx.x;   // d-pair index, d = 2dp, 2dp+1
    int h  = blockIdx.y;
    int b  = blockIdx.z;
    __shared__ float sm[2][T2][RR + 1];
    __shared__ float cf[2][T2];
    const int tid = threadIdx.x;
    const float scale = rsqrtf((float)(RR * DD)) * ZSCALE;

    if (tid < 2*T2) {
        int dd = tid / T2, t = tid - dd*T2;
        float x = gains[(h*DD + dp*2 + dd)*SS + (t % SS)];
        cf[dd][t] = (fmaxf(x, 0.0f) + log1pf(expf(-fabsf(x)))) * scale;
    }
    if (b == 0 && tid >= 64 && tid < 64 + 2*SS) {
        int u = tid - 64;
        int dd = u / SS, s = u - dd*SS;
        int gi = (h*DD + dp*2 + dd)*SS + s;
        float f = freqs[gi];
        float tp = 6.28318530717958647692f * (0.5f / (1.0f + expf(-f)));
        g_tpfr[gi] = tp;
        float so, co;
        sincosf(offsets[gi], &so, &co);
        g_co[gi] = co;
        g_so[gi] = so;
        float s1, c1;
        sincosf(tp, &s1, &c1);
        g_c1[gi] = c1;
        g_s1[gi] = s1;
    }
    __syncthreads();

    const float* zd = zg + (((size_t)(b*HH + h)*DD + dp*2)*T2)*RR;
    for (int i = tid; i < 2*T2*RR; i += 128) {
        int dd  = i / (T2*RR);
        int rem = i - dd*(T2*RR);
        int t = rem >> 7, r = rem & 127;
        sm[dd][t][r] = zd[i] * cf[dd][t];
    }
    __syncthreads();

    const int r = tid;   // 0..127
    uint32_t pkh[20], pkl[20];
    #pragma unroll
    for (int dd = 0; dd < 2; ++dd)
        #pragma unroll
        for (int j = 0; j < 10; ++j) {
            float v0 = sm[dd][2*j][r], v1 = sm[dd][2*j + 1][r];
            __half h0 = __float2half_rn(v0), h1 = __float2half_rn(v1);
            __half2 hh = __halves2half2(h0, h1);
            pkh[dd*10 + j] = *(uint32_t*)&hh;
            pkl[dd*10 + j] = h2(v0 - __half2float(h0), v1 - __half2float(h1));
        }

    size_t ob = ((size_t)(b*HH + h)*RR + r)*KTOT + (size_t)dp*2*T2;  // halves
    uint4* dh = (uint4*)(g_zThi + ob);
    uint4* dl = (uint4*)(g_zTlo + ob);
    #pragma unroll
    for (int v = 0; v < 5; ++v) {
        dh[v] = make_uint4(pkh[4*v], pkh[4*v+1], pkh[4*v+2], pkh[4*v+3]);
        dl[v] = make_uint4(pkl[4*v], pkl[4*v+1], pkl[4*v+2], pkl[4*v+3]);
    }
}

// ---------------- main HMMA kernel ----------------
__global__ __launch_bounds__(256, 2)
void spe_mma_main(const float* __restrict__ qg,
                  const float* __restrict__ kg,
                  float* __restrict__ out) {
    extern __shared__ char smraw[];
    const uint32_t sb   = smem_u32(smraw);
    const uint32_t tb_u = (sb + 1023) & ~1023u;
    char* tb = smraw + (tb_u - sb);

    const int tid  = threadIdx.x;
    const int wid  = tid >> 5;
    const int lane = tid & 31;
    const int l0   = blockIdx.x * MT;
    const int h    = blockIdx.y;
    const int b    = blockIdx.z;

    const int mi = wid & 1;   // 2 m32 blocks
    const int ni = wid >> 1;  // 4 n32 blocks

    const __half* zThi = g_zThi + (size_t)(b*HH + h)*RR*KTOT;
    const __half* zTlo = g_zTlo + (size_t)(b*HH + h)*RR*KTOT;

    // ---- stageB: cp.async B hi/lo tiles of chunk ch into buffer buf ----
    auto stageB = [&](int ch, int buf) {
        const int k0 = ch * KC;
        const uint32_t bh = tb_u + buf*BUFSZ + OFF_BH;
        const uint32_t bl = tb_u + buf*BUFSZ + OFF_BL;
        #pragma unroll
        for (int u = 0; u < 4; ++u) {
            int idx = tid + u*256;           // 1024 units of 8 fp16
            int r   = idx >> 3;
            int kl8 = (idx & 7) * 8;
            uint32_t byte = swz((uint32_t)(r*128 + kl8*2));
            size_t gsrc = (size_t)r*KTOT + k0 + kl8;
            cp16(bh + byte, zThi + gsrc);
            cp16(bl + byte, zTlo + gsrc);
        }
        asm volatile("cp.async.commit_group;" ::: "memory");
    };

    // ---- A-staging state (thread owns k-pair pi, l-strip of 8) ----
    const int pi = tid & 31;
    const int lb = (tid >> 5) * 8;
    float st_cp, st_sp, st_c1, st_s1, st_co, st_so;
    float st_qv[8], st_kv[8];

    // prep chunk ch: tables, anchor sincos, prefetch q/k
    auto prep = [&](int ch) {
        const int k  = ch*KC + 2*pi;
        const int d  = k / T2;
        const int s  = (k - d*T2) >> 1;
        const int gb = (h*DD + d)*SS + s;
        float tp = g_tpfr[gb];
        sincosf(tp * (float)(l0 + lb), &st_sp, &st_cp);
        st_c1 = g_c1[gb]; st_s1 = g_s1[gb];
        st_co = g_co[gb]; st_so = g_so[gb];
        const float* qp = qg + ((((size_t)b*LL + l0 + lb)*HH + h)*DD + d);
        const float* kp = kg + ((((size_t)b*LL + l0 + lb)*HH + h)*DD + d);
        #pragma unroll
        for (int i = 0; i < 8; ++i) {
            st_qv[i] = __ldg(qp + (size_t)i*(HH*DD));
            st_kv[i] = __ldg(kp + (size_t)i*(HH*DD));
        }
    };

    // stage 2 l's of the prepped chunk into buffer buf (A is single fp16 now)
    auto partA = [&](int buf, int i0) {
        char* tile = tb + buf*BUFSZ;
        #pragma unroll
        for (int ii = 0; ii < 2; ++ii) {
            int i = i0 + ii;
            float cq = st_cp*st_co - st_sp*st_so;
            float sq = st_sp*st_co + st_cp*st_so;
            uint32_t byte = swz((uint32_t)((lb + i)*128 + pi*4));
            *(uint32_t*)(tile + OFF_AQ + byte) = h2(cq*st_qv[i], sq*st_qv[i]);
            *(uint32_t*)(tile + OFF_AK + byte) = h2(st_cp*st_kv[i], st_sp*st_kv[i]);
            float ncp = st_cp*st_c1 - st_sp*st_s1;
            float nsp = st_sp*st_c1 + st_cp*st_s1;
            st_cp = ncp; st_sp = nsp;
        }
    };

    // accumulators: [msub 2][ntile 4][4] for q and k
    float accq[2][4][4];
    float acck[2][4][4];
    #pragma unroll
    for (int i = 0; i < 2; ++i)
        #pragma unroll
        for (int j = 0; j < 4; ++j)
            #pragma unroll
            for (int c = 0; c < 4; ++c) { accq[i][j][c] = 0.0f; acck[i][j][c] = 0.0f; }

    const uint32_t lanerow = lane & 15;
    const uint32_t lanecol = (uint32_t)(lane >> 4) * 16;

    // prologue: fill buffer 0 with chunk 0
    stageB(0, 0);
    prep(0);
    partA(0, 0); partA(0, 2); partA(0, 4); partA(0, 6);
    asm volatile("cp.async.wait_group 0;" ::: "memory");
    __syncthreads();

    #pragma unroll 1
    for (int ch = 0; ch < NCH; ++ch) {
        const int buf = ch & 1;
        const bool more = (ch + 1 < NCH);
        if (more) { stageB(ch + 1, buf ^ 1); prep(ch + 1); }

        const uint32_t base = tb_u + buf*BUFSZ;
        #pragma unroll
        for (int kk = 0; kk < 4; ++kk) {
            const uint32_t kb = kk * 32;   // 16 elems * 2B
            // --- B fragments hi+lo (shared by q and k) ---
            uint32_t bh[4][2], bl[4][2];
            {
                uint32_t t0[4], t1[4];
                uint32_t o0 = swz((ni*32 +  0 + lanerow)*128 + lanecol + kb);
                uint32_t o1 = swz((ni*32 + 16 + lanerow)*128 + lanecol + kb);
                ldsm4(t0, base + OFF_BH + o0);
                ldsm4(t1, base + OFF_BH + o1);
                bh[0][0]=t0[0]; bh[0][1]=t0[2]; bh[1][0]=t0[1]; bh[1][1]=t0[3];
                bh[2][0]=t1[0]; bh[2][1]=t1[2]; bh[3][0]=t1[1]; bh[3][1]=t1[3];
                ldsm4(t0, base + OFF_BL + o0);
                ldsm4(t1, base + OFF_BL + o1);
                bl[0][0]=t0[0]; bl[0][1]=t0[2]; bl[1][0]=t0[1]; bl[1][1]=t0[3];
                bl[2][0]=t1[0]; bl[2][1]=t1[2]; bl[3][0]=t1[1]; bl[3][1]=t1[3];
            }
            const uint32_t a0 = swz((mi*32 +  0 + lanerow)*128 + lanecol + kb);
            const uint32_t a1 = swz((mi*32 + 16 + lanerow)*128 + lanecol + kb);
            // --- q: a * (bh + bl) ---
            {
                uint32_t aq[2][4];
                ldsm4(aq[0], base + OFF_AQ + a0);
                ldsm4(aq[1], base + OFF_AQ + a1);
                #pragma unroll
                for (int s = 0; s < 2; ++s)
                    #pragma unroll
                    for (int j = 0; j < 4; ++j) {
                        mma16816(accq[s][j], aq[s], bh[j]);
                        mma16816(accq[s][j], aq[s], bl[j]);
                    }
            }
            // --- k: a * (bh + bl) ---
            {
                uint32_t ak[2][4];
                ldsm4(ak[0], base + OFF_AK + a0);
                ldsm4(ak[1], base + OFF_AK + a1);
                #pragma unroll
                for (int s = 0; s < 2; ++s)
                    #pragma unroll
                    for (int j = 0; j < 4; ++j) {
                        mma16816(acck[s][j], ak[s], bh[j]);
                        mma16816(acck[s][j], ak[s], bl[j]);
                    }
            }
            // --- interleaved A staging for chunk ch+1 (2 of 8 l's) ---
            if (more) partA(buf ^ 1, 2*kk);
        }

        asm volatile("cp.async.wait_group 0;" ::: "memory");
        __syncthreads();
    }

    // ---- epilogue: c-frag scatter (undo ZSCALE) ----
    const size_t khat_off = (size_t)BB * LL * HH * RR;
    #pragma unroll
    for (int s = 0; s < 2; ++s) {
        int row0 = l0 + mi*32 + s*16 + (lane >> 2);
        #pragma unroll
        for (int j = 0; j < 4; ++j) {
            int col = ni*32 + j*8 + (lane & 3)*2;
            size_t oA = (((size_t)b*LL + row0)*HH + h)*RR + col;
            size_t oB = oA + (size_t)8*HH*RR;   // row0 + 8
            *(float2*)(out + oA) = make_float2(accq[s][j][0]*ZUNSCALE, accq[s][j][1]*ZUNSCALE);
            *(float2*)(out + oB) = make_float2(accq[s][j][2]*ZUNSCALE, accq[s][j][3]*ZUNSCALE);
            *(float2*)(out + khat_off + oA) = make_float2(acck[s][j][0]*ZUNSCALE, acck[s][j][1]*ZUNSCALE);
            *(float2*)(out + khat_off + oB) = make_float2(acck[s][j][2]*ZUNSCALE, acck[s][j][3]*ZUNSCALE);
        }
    }
}

extern "C" void kernel_launch(void* const* d_in, const int* in_sizes, int n_in,
                              void* d_out, int out_size) {
    const float* queries = (const float*)d_in[0];
    const float* keys    = (const float*)d_in[1];
    const float* freqs   = (const float*)d_in[2];
    const float* offsets = (const float*)d_in[3];
    const float* gains   = (const float*)d_in[4];
    const float* z       = (const float*)d_in[5];
    float* out = (float*)d_out;

    cudaFuncSetAttribute(spe_mma_main, cudaFuncAttributeMaxDynamicSharedMemorySize, SMEM_BYTES);

    spe_transpose<<<dim3(DD/2, HH, BB), 128>>>(z, freqs, offsets, gains);
    spe_mma_main<<<dim3(LL/MT, HH, BB), 256, SMEM_BYTES>>>(queries, keys, out);
}

// round 11
// speedup vs baseline: 1.5820x; 1.5820x over previous
#include <cuda_runtime.h>
#include <cuda_fp16.h>
#include <math.h>
#include <stdint.h>

#define BB 2
#define LL 1024
#define HH 8
#define DD 64
#define SS 10
#define T2 20      // 2S
#define RR 128
#define KTOT 1280  // DD*T2
#define KC 64      // K per chunk
#define NCH 20     // KTOT/KC
#define MT 64      // M tile (l) per CTA

#define TSZA 8192            // 64x64 fp16 tile (128B rows, SW128)
#define TSZB 16384           // 128x64 fp16 tile
#define OFF_AQ 0
#define OFF_AK (1*TSZA)
#define OFF_B  (2*TSZA)
#define BUFSZ (2*TSZA + TSZB)     // 32 KB
#define SMEM_BYTES (2*BUFSZ + 1024)

#define ZSCALE 64.0f         // keeps small zs values well inside fp16 normal range
#define ZUNSCALE (1.0f/64.0f)

static __device__ __align__(16) __half g_zT[(size_t)BB*HH*RR*KTOT];

__device__ float g_tpfr[HH*DD*SS];   // 2*pi*sigmoid(freqs)/2
__device__ float g_co[HH*DD*SS];     // cos(offsets)
__device__ float g_so[HH*DD*SS];     // sin(offsets)
__device__ float g_c1[HH*DD*SS];     // cos(tpfr)  (rotation per +1 in l)
__device__ float g_s1[HH*DD*SS];     // sin(tpfr)

// ---------------- helpers ----------------
__device__ __forceinline__ uint32_t smem_u32(const void* p) {
    uint32_t a;
    asm("{ .reg .u64 t; cvta.to.shared.u64 t, %1; cvt.u32.u64 %0, t; }" : "=r"(a) : "l"(p));
    return a;
}
__device__ __forceinline__ uint32_t swz(uint32_t b) { return b ^ ((b >> 3) & 0x70); }
__device__ __forceinline__ uint32_t h2(float x, float y) {
    __half2 h = __floats2half2_rn(x, y);
    return *(uint32_t*)&h;
}
__device__ __forceinline__ void ldsm4(uint32_t* r, uint32_t a) {
    asm volatile("ldmatrix.sync.aligned.m8n8.x4.shared.b16 {%0,%1,%2,%3}, [%4];"
        : "=r"(r[0]), "=r"(r[1]), "=r"(r[2]), "=r"(r[3]) : "r"(a));
}
__device__ __forceinline__ void mma16816(float* d, const uint32_t* a, const uint32_t* b) {
    asm volatile(
        "mma.sync.aligned.m16n8k16.row.col.f32.f16.f16.f32 "
        "{%0,%1,%2,%3}, {%4,%5,%6,%7}, {%8,%9}, {%0,%1,%2,%3};"
        : "+f"(d[0]), "+f"(d[1]), "+f"(d[2]), "+f"(d[3])
        : "r"(a[0]), "r"(a[1]), "r"(a[2]), "r"(a[3]), "r"(b[0]), "r"(b[1]));
}
__device__ __forceinline__ void cp16(uint32_t dst, const void* src) {
    asm volatile("cp.async.cg.shared.global [%0], [%1], 16;" :: "r"(dst), "l"(src) : "memory");
}

// ---------------- transpose + coef-scale -> fp16 (+ table fill) ----------------
// z[b][h][d][t][r] (fp32) -> zT[b][h][r][d*20+t] (fp16, scaled by ZSCALE)
// One block handles 2 consecutive d.
__global__ __launch_bounds__(128)
void spe_transpose(const float* __restrict__ zg,
                   const float* __restrict__ freqs,
                   const float* __restrict__ offsets,
                   const float* __restrict__ gains) {
    int dp = blockIdx.x;   // d-pair index, d = 2dp, 2dp+1
    int h  = blockIdx.y;
    int b  = blockIdx.z;
    __shared__ float sm[2][T2][RR + 1];
    __shared__ float cf[2][T2];
    const int tid = threadIdx.x;
    const float scale = rsqrtf((float)(RR * DD)) * ZSCALE;

    if (tid < 2*T2) {
        int dd = tid / T2, t = tid - dd*T2;
        float x = gains[(h*DD + dp*2 + dd)*SS + (t % SS)];
        cf[dd][t] = (fmaxf(x, 0.0f) + log1pf(expf(-fabsf(x)))) * scale;
    }
    if (b == 0 && tid >= 64 && tid < 64 + 2*SS) {
        int u = tid - 64;
        int dd = u / SS, s = u - dd*SS;
        int gi = (h*DD + dp*2 + dd)*SS + s;
        float f = freqs[gi];
        float tp = 6.28318530717958647692f * (0.5f / (1.0f + expf(-f)));
        g_tpfr[gi] = tp;
        float so, co;
        sincosf(offsets[gi], &so, &co);
        g_co[gi] = co;
        g_so[gi] = so;
        float s1, c1;
        sincosf(tp, &s1, &c1);
        g_c1[gi] = c1;
        g_s1[gi] = s1;
    }
    __syncthreads();

    const float* zd = zg + (((size_t)(b*HH + h)*DD + dp*2)*T2)*RR;
    for (int i = tid; i < 2*T2*RR; i += 128) {
        int dd  = i / (T2*RR);
        int rem = i - dd*(T2*RR);
        int t = rem >> 7, r = rem & 127;
        sm[dd][t][r] = zd[i] * cf[dd][t];
    }
    __syncthreads();

    const int r = tid;   // 0..127
    uint32_t pk[20];
    #pragma unroll
    for (int dd = 0; dd < 2; ++dd)
        #pragma unroll
        for (int j = 0; j < 10; ++j)
            pk[dd*10 + j] = h2(sm[dd][2*j][r], sm[dd][2*j + 1][r]);

    size_t ob = ((size_t)(b*HH + h)*RR + r)*KTOT + (size_t)dp*2*T2;  // halves
    uint4* dst = (uint4*)(g_zT + ob);
    #pragma unroll
    for (int v = 0; v < 5; ++v)
        dst[v] = make_uint4(pk[4*v], pk[4*v+1], pk[4*v+2], pk[4*v+3]);
}

// ---------------- main HMMA kernel ----------------
__global__ __launch_bounds__(256, 2)
void spe_mma_main(const float* __restrict__ qg,
                  const float* __restrict__ kg,
                  float* __restrict__ out) {
    extern __shared__ char smraw[];
    const uint32_t sb   = smem_u32(smraw);
    const uint32_t tb_u = (sb + 1023) & ~1023u;
    char* tb = smraw + (tb_u - sb);

    const int tid  = threadIdx.x;
    const int wid  = tid >> 5;
    const int lane = tid & 31;
    const int l0   = blockIdx.x * MT;
    const int h    = blockIdx.y;
    const int b    = blockIdx.z;

    const int mi = wid & 1;   // 2 m32 blocks
    const int ni = wid >> 1;  // 4 n32 blocks

    const __half* zT = g_zT + (size_t)(b*HH + h)*RR*KTOT;

    // ---- stageB: cp.async B tile of chunk ch into buffer buf ----
    auto stageB = [&](int ch, int buf) {
        const int k0 = ch * KC;
        const uint32_t base = tb_u + buf*BUFSZ + OFF_B;
        #pragma unroll
        for (int u = 0; u < 4; ++u) {
            int idx = tid + u*256;           // 1024 units of 8 fp16
            int r   = idx >> 3;
            int kl8 = (idx & 7) * 8;
            uint32_t byte = swz((uint32_t)(r*128 + kl8*2));
            cp16(base + byte, zT + (size_t)r*KTOT + k0 + kl8);
        }
        asm volatile("cp.async.commit_group;" ::: "memory");
    };

    // ---- A-staging state (thread owns k-pair pi, l-strip of 8) ----
    const int pi = tid & 31;
    const int lb = (tid >> 5) * 8;
    float st_cp, st_sp, st_c1, st_s1, st_co, st_so;
    float st_qv[8], st_kv[8];

    // prep chunk ch: tables, anchor sincos, prefetch q/k
    auto prep = [&](int ch) {
        const int k  = ch*KC + 2*pi;
        const int d  = k / T2;
        const int s  = (k - d*T2) >> 1;
        const int gb = (h*DD + d)*SS + s;
        float tp = g_tpfr[gb];
        sincosf(tp * (float)(l0 + lb), &st_sp, &st_cp);
        st_c1 = g_c1[gb]; st_s1 = g_s1[gb];
        st_co = g_co[gb]; st_so = g_so[gb];
        const float* qp = qg + ((((size_t)b*LL + l0 + lb)*HH + h)*DD + d);
        const float* kp = kg + ((((size_t)b*LL + l0 + lb)*HH + h)*DD + d);
        #pragma unroll
        for (int i = 0; i < 8; ++i) {
            st_qv[i] = __ldg(qp + (size_t)i*(HH*DD));
            st_kv[i] = __ldg(kp + (size_t)i*(HH*DD));
        }
    };

    // stage 2 l's of the prepped chunk into buffer buf
    auto partA = [&](int buf, int i0) {
        char* tile = tb + buf*BUFSZ;
        #pragma unroll
        for (int ii = 0; ii < 2; ++ii) {
            int i = i0 + ii;
            float cq = st_cp*st_co - st_sp*st_so;
            float sq = st_sp*st_co + st_cp*st_so;
            uint32_t byte = swz((uint32_t)((lb + i)*128 + pi*4));
            *(uint32_t*)(tile + OFF_AQ + byte) = h2(cq*st_qv[i], sq*st_qv[i]);
            *(uint32_t*)(tile + OFF_AK + byte) = h2(st_cp*st_kv[i], st_sp*st_kv[i]);
            float ncp = st_cp*st_c1 - st_sp*st_s1;
            float nsp = st_sp*st_c1 + st_cp*st_s1;
            st_cp = ncp; st_sp = nsp;
        }
    };

    // accumulators: [msub 2][ntile 4][4] for q and k
    float accq[2][4][4];
    float acck[2][4][4];
    #pragma unroll
    for (int i = 0; i < 2; ++i)
        #pragma unroll
        for (int j = 0; j < 4; ++j)
            #pragma unroll
            for (int c = 0; c < 4; ++c) { accq[i][j][c] = 0.0f; acck[i][j][c] = 0.0f; }

    const uint32_t lanerow = lane & 15;
    const uint32_t lanecol = (uint32_t)(lane >> 4) * 16;

    // prologue: fill buffer 0 with chunk 0
    stageB(0, 0);
    prep(0);
    partA(0, 0); partA(0, 2); partA(0, 4); partA(0, 6);
    asm volatile("cp.async.wait_group 0;" ::: "memory");
    __syncthreads();

    #pragma unroll 1
    for (int ch = 0; ch < NCH; ++ch) {
        const int buf = ch & 1;
        const bool more = (ch + 1 < NCH);
        if (more) { stageB(ch + 1, buf ^ 1); prep(ch + 1); }

        const uint32_t base = tb_u + buf*BUFSZ;
        #pragma unroll
        for (int kk = 0; kk < 4; ++kk) {
            const uint32_t kb = kk * 32;   // 16 elems * 2B
            // --- B fragments (shared by q and k) ---
            uint32_t bh[4][2];
            {
                uint32_t t0[4], t1[4];
                uint32_t o0 = swz((ni*32 +  0 + lanerow)*128 + lanecol + kb);
                uint32_t o1 = swz((ni*32 + 16 + lanerow)*128 + lanecol + kb);
                ldsm4(t0, base + OFF_B + o0);
                ldsm4(t1, base + OFF_B + o1);
                bh[0][0]=t0[0]; bh[0][1]=t0[2]; bh[1][0]=t0[1]; bh[1][1]=t0[3];
                bh[2][0]=t1[0]; bh[2][1]=t1[2]; bh[3][0]=t1[1]; bh[3][1]=t1[3];
            }
            const uint32_t a0 = swz((mi*32 +  0 + lanerow)*128 + lanecol + kb);
            const uint32_t a1 = swz((mi*32 + 16 + lanerow)*128 + lanecol + kb);
            // --- q ---
            {
                uint32_t aq[2][4];
                ldsm4(aq[0], base + OFF_AQ + a0);
                ldsm4(aq[1], base + OFF_AQ + a1);
                #pragma unroll
                for (int s = 0; s < 2; ++s)
                    #pragma unroll
                    for (int j = 0; j < 4; ++j)
                        mma16816(accq[s][j], aq[s], bh[j]);
            }
            // --- k ---
            {
                uint32_t ak[2][4];
                ldsm4(ak[0], base + OFF_AK + a0);
                ldsm4(ak[1], base + OFF_AK + a1);
                #pragma unroll
                for (int s = 0; s < 2; ++s)
                    #pragma unroll
                    for (int j = 0; j < 4; ++j)
                        mma16816(acck[s][j], ak[s], bh[j]);
            }
            // --- interleaved A staging for chunk ch+1 (2 of 8 l's) ---
            if (more) partA(buf ^ 1, 2*kk);
        }

        asm volatile("cp.async.wait_group 0;" ::: "memory");
        __syncthreads();
    }

    // ---- epilogue: c-frag scatter (undo ZSCALE) ----
    const size_t khat_off = (size_t)BB * LL * HH * RR;
    #pragma unroll
    for (int s = 0; s < 2; ++s) {
        int row0 = l0 + mi*32 + s*16 + (lane >> 2);
        #pragma unroll
        for (int j = 0; j < 4; ++j) {
            int col = ni*32 + j*8 + (lane & 3)*2;
            size_t oA = (((size_t)b*LL + row0)*HH + h)*RR + col;
            size_t oB = oA + (size_t)8*HH*RR;   // row0 + 8
            *(float2*)(out + oA) = make_float2(accq[s][j][0]*ZUNSCALE, accq[s][j][1]*ZUNSCALE);
            *(float2*)(out + oB) = make_float2(accq[s][j][2]*ZUNSCALE, accq[s][j][3]*ZUNSCALE);
            *(float2*)(out + khat_off + oA) = make_float2(acck[s][j][0]*ZUNSCALE, acck[s][j][1]*ZUNSCALE);
            *(float2*)(out + khat_off + oB) = make_float2(acck[s][j][2]*ZUNSCALE, acck[s][j][3]*ZUNSCALE);
        }
    }
}

extern "C" void kernel_launch(void* const* d_in, const int* in_sizes, int n_in,
                              void* d_out, int out_size) {
    const float* queries = (const float*)d_in[0];
    const float* keys    = (const float*)d_in[1];
    const float* freqs   = (const float*)d_in[2];
    const float* offsets = (const float*)d_in[3];
    const float* gains   = (const float*)d_in[4];
    const float* z       = (const float*)d_in[5];
    float* out = (float*)d_out;

    cudaFuncSetAttribute(spe_mma_main, cudaFuncAttributeMaxDynamicSharedMemorySize, SMEM_BYTES);

    spe_transpose<<<dim3(DD/2, HH, BB), 128>>>(z, freqs, offsets, gains);
    spe_mma_main<<<dim3(LL/MT, HH, BB), 256, SMEM_BYTES>>>(queries, keys, out);
}